// round 16
// baseline (speedup 1.0000x reference)
#include <cuda_runtime.h>

#define NUM_FACES 13776
#define MAXC 8
#define EPSF 1e-8f
#define PADF 13824                    // pad to multiple of 64 (48 sentinels)
#define K2_BLOCKS (NUM_FACES / 16)    // 861 blocks, 8 warps, 2 rows per warp

// ---- device scratch (static; no runtime allocations) ----
__device__ float4 g_bb0[PADF];        // (lo.xyz, bits(i0|i1<<16))
__device__ float4 g_bb1[PADF];        // (hi.xyz, bits(i2))
__device__ float4 g_tv[NUM_FACES*3];  // per-face vertices (xyz, -)
__device__ float4 g_n[NUM_FACES];     // per-face unit normal (xyz, -)
__device__ float4 g_c[NUM_FACES];     // per-face centroid (xyz, -)
__device__ double g_accum;            // self-resetting
__device__ unsigned g_done;           // self-resetting

// ---------------------------------------------------------------------------
// Kernel 1: FOUR lanes per face (216 blocks x 256 -> 3 scattered loads/lane,
// high occupancy). Lane0 of each quad computes AABB + normal + centroid.
// ---------------------------------------------------------------------------
__global__ void __launch_bounds__(256) setup_kernel(
        const float* __restrict__ verts, const int* __restrict__ faces) {
    int gt = (int)blockIdx.x * 256 + threadIdx.x;  // 216*256 = 55296 = 4*PADF
    int f = gt >> 2;
    int l = gt & 3;
    int wl = threadIdx.x & 31;
    int qb = wl & ~3;                               // quad base lane

    if (f >= PADF) return;
    bool real = f < NUM_FACES;
    int fc = real ? f : (NUM_FACES - 1);            // clamp keeps quads converged
    int comp = (l < 2) ? l : 2;                     // lane 3 duplicates lane 2
    int idx = faces[3 * fc + comp];
    float x = verts[3 * idx + 0];
    float y = verts[3 * idx + 1];
    float z = verts[3 * idx + 2];

    if (real && l < 3) g_tv[f*3 + l] = make_float4(x, y, z, 0.f);

    // gather v1,v2 coords to lane0 of the quad
    float x1 = __shfl_sync(0xffffffffu, x, qb + 1);
    float y1 = __shfl_sync(0xffffffffu, y, qb + 1);
    float z1 = __shfl_sync(0xffffffffu, z, qb + 1);
    float x2 = __shfl_sync(0xffffffffu, x, qb + 2);
    float y2 = __shfl_sync(0xffffffffu, y, qb + 2);
    float z2 = __shfl_sync(0xffffffffu, z, qb + 2);
    int i1 = __shfl_sync(0xffffffffu, idx, qb + 1);
    int i2 = __shfl_sync(0xffffffffu, idx, qb + 2);

    if (l == 0) {
        if (!real) {                                // sentinel: never overlaps
            g_bb0[f] = make_float4(1e30f, 1e30f, 1e30f, __int_as_float(-1));
            g_bb1[f] = make_float4(-1e30f, -1e30f, -1e30f, __int_as_float(-1));
            return;
        }
        float mnx = fminf(x, fminf(x1, x2)), mxx = fmaxf(x, fmaxf(x1, x2));
        float mny = fminf(y, fminf(y1, y2)), mxy = fmaxf(y, fmaxf(y1, y2));
        float mnz = fminf(z, fminf(z1, z2)), mxz = fmaxf(z, fmaxf(z1, z2));
        g_bb0[f] = make_float4(mnx, mny, mnz, __int_as_float(idx | (i1 << 16)));
        g_bb1[f] = make_float4(mxx, mxy, mxz, __int_as_float(i2));

        float e0x = x1-x, e0y = y1-y, e0z = z1-z;
        float e1x = x2-x, e1y = y2-y, e1z = z2-z;
        float nx = e0y*e1z - e0z*e1y;
        float ny = e0z*e1x - e0x*e1z;
        float nz = e0x*e1y - e0y*e1x;
        float inv = 1.0f / (sqrtf(nx*nx + ny*ny + nz*nz) + EPSF);
        g_n[f] = make_float4(nx*inv, ny*inv, nz*inv, 0.f);
        g_c[f] = make_float4((x+x1+x2)*(1.0f/3.0f),
                             (y+y1+y2)*(1.0f/3.0f),
                             (z+z1+z2)*(1.0f/3.0f), 0.f);
    }
}

// Cone-field penalty with precomputed (n, c). SIGMA=0.5 -> *2 exact.
__device__ __forceinline__ float cone_pen_nc(float4 n, float4 c,
                                             float4 p0, float4 p1, float4 p2) {
    float pen = 0.0f;
#pragma unroll
    for (int v = 0; v < 3; v++) {
        float4 p = (v == 0) ? p0 : (v == 1) ? p1 : p2;
        float ux = p.x - c.x, uy = p.y - c.y, uz = p.z - c.z;
        float h = ux*n.x + uy*n.y + uz*n.z;
        float wx = ux - h*n.x, wy = uy - h*n.y, wz = uz - h*n.z;
        float r = sqrtf(wx*wx + wy*wy + wz*wz);
        float radial = fmaxf(1.0f - r*2.0f, 0.0f);
        float depth = fmaxf(-h, 0.0f) + fmaxf(h, 0.0f) * __expf(-h*2.0f);
        float phi = radial * depth;
        pen += phi * phi;
    }
    return pen;
}

__device__ __forceinline__ bool share_ids(int rf0, int rf1, int rf2,
                                          int jp, int jf2) {
    int jf0 = jp & 0xFFFF, jf1 = jp >> 16;
    return (rf0 == jf0) | (rf0 == jf1) | (rf0 == jf2) |
           (rf1 == jf0) | (rf1 == jf1) | (rf1 == jf2) |
           (rf2 == jf0) | (rf2 == jf1) | (rf2 == jf2);
}

// ---------------------------------------------------------------------------
// Kernel 2: TWO rows per warp, chunk-PAIR pipelined scan (both chunks' loads
// issued before processing -> 2x load-level parallelism on the critical
// chain), 32-lane eval with precomputed normals, fused finalize.
// ---------------------------------------------------------------------------
__global__ void __launch_bounds__(256) collide_kernel(float* __restrict__ out) {
    __shared__ int    s_j[8][16];     // [warp][pair + 8*rowsel]
    __shared__ double s_bsum;

    int tid = threadIdx.x;
    int lane = tid & 31;
    int wwid = tid >> 5;
    int row0 = ((int)blockIdx.x * 8 + wwid) * 2;   // 861*8*2 = 13776 exactly
    int row1 = row0 + 1;
    unsigned below = (1u << lane) - 1u;
    if (tid == 0) s_bsum = 0.0;

    float4 amin = g_bb0[row0], amax = g_bb1[row0];
    float4 bmin = g_bb0[row1], bmax = g_bb1[row1];
    int ap = __float_as_int(amin.w);
    int af0 = ap & 0xFFFF, af1 = ap >> 16, af2 = __float_as_int(amax.w);
    int bp = __float_as_int(bmin.w);
    int bf0 = bp & 0xFFFF, bf1 = bp >> 16, bf2 = __float_as_int(bmax.w);

    int found0 = 0, found1 = 0;

#define PROC_CHUNK(JA, JB, JIDX)                                              \
    do {                                                                      \
        int jp_ = __float_as_int((JA).w);                                     \
        int jf2_ = __float_as_int((JB).w);                                    \
        bool ok0 = (amin.x <= (JB).x) && ((JA).x <= amax.x) &&                \
                   (amin.y <= (JB).y) && ((JA).y <= amax.y) &&                \
                   (amin.z <= (JB).z) && ((JA).z <= amax.z);                  \
        if (ok0) ok0 = !share_ids(af0, af1, af2, jp_, jf2_);                  \
        bool ok1 = (bmin.x <= (JB).x) && ((JA).x <= bmax.x) &&                \
                   (bmin.y <= (JB).y) && ((JA).y <= bmax.y) &&                \
                   (bmin.z <= (JB).z) && ((JA).z <= bmax.z);                  \
        if (ok1) ok1 = !share_ids(bf0, bf1, bf2, jp_, jf2_);                  \
        unsigned m0 = __ballot_sync(0xffffffffu, ok0);                        \
        unsigned m1 = __ballot_sync(0xffffffffu, ok1);                        \
        int r0_ = found0 + __popc(m0 & below);                                \
        int r1_ = found1 + __popc(m1 & below);                                \
        if (ok0 && r0_ < MAXC) s_j[wwid][r0_] = (JIDX);                       \
        if (ok1 && r1_ < MAXC) s_j[wwid][8 + r1_] = (JIDX);                   \
        found0 += __popc(m0);                                                 \
        found1 += __popc(m1);                                                 \
    } while (0)

    for (int base = 0; base < PADF && (found0 < MAXC || found1 < MAXC);
         base += 64) {
        int j0 = base + lane;
        int j1 = base + 32 + lane;
        float4 ja0 = g_bb0[j0];                    // all 4 loads issue before
        float4 jb0 = g_bb1[j0];                    // any processing
        float4 ja1 = g_bb0[j1];
        float4 jb1 = g_bb1[j1];
        PROC_CHUNK(ja0, jb0, j0);
        if (found0 < MAXC || found1 < MAXC)        // warp-uniform
            PROC_CHUNK(ja1, jb1, j1);
    }
#undef PROC_CHUNK

    if (found0 > MAXC) found0 = MAXC;
    if (found1 > MAXC) found1 = MAXC;
    __syncwarp();

    // narrow phase: 32 lanes -> (row l>>4) x (pair (l&15)>>1) x (dir l&1)
    int rowsel = lane >> 4;
    int l = lane & 15;
    int pairIdx = l >> 1;
    int cnt = rowsel ? found1 : found0;
    float pen = 0.0f;
    if (pairIdx < cnt) {
        int row = rowsel ? row1 : row0;
        int j = s_j[wwid][(rowsel << 3) + pairIdx];
        int srcF = (l & 1) ? j : row;              // field-generating tri
        int ptsF = (l & 1) ? row : j;              // query vertices
        float4 n = g_n[srcF];
        float4 c = g_c[srcF];
        float4 p0 = g_tv[ptsF*3+0];
        float4 p1 = g_tv[ptsF*3+1];
        float4 p2 = g_tv[ptsF*3+2];
        pen = cone_pen_nc(n, c, p0, p1, p2);
    }
#pragma unroll
    for (int off = 16; off > 0; off >>= 1)
        pen += __shfl_xor_sync(0xffffffffu, pen, off);
    if (lane == 0 && pen != 0.0f) atomicAdd(&s_bsum, (double)pen);
    __syncthreads();

    // fused finalize: last-arriving block writes output + resets state
    if (tid == 0) {
        if (s_bsum != 0.0) atomicAdd(&g_accum, s_bsum);
        __threadfence();
        unsigned old = atomicAdd(&g_done, 1u);
        if (old == K2_BLOCKS - 1) {
            g_done = 0;                             // reset for graph replay
            unsigned long long bits =
                atomicExch((unsigned long long*)&g_accum, 0ULL);
            out[0] = (float)__longlong_as_double(bits);  // weight = 1.0
        }
    }
}

extern "C" void kernel_launch(void* const* d_in, const int* in_sizes, int n_in,
                              void* d_out, int out_size) {
    const float* verts = (const float*)d_in[0];
    const int*   faces = (const int*)d_in[1];
    float*       out   = (float*)d_out;

    setup_kernel<<<(4 * PADF) / 256, 256>>>(verts, faces);
    collide_kernel<<<K2_BLOCKS, 256>>>(out);
}

// round 17
// speedup vs baseline: 1.1056x; 1.1056x over previous
#include <cuda_runtime.h>

#define NUM_FACES 13776
#define MAXC 8
#define EPSF 1e-8f
#define PADF 13824                    // pad to multiple of 64 (48 sentinels)
#define K2_BLOCKS (NUM_FACES / 16)    // 861 blocks, 8 warps, 2 rows per warp

// ---- device scratch (static; no runtime allocations) ----
__device__ float4 g_bb0[PADF];        // (lo.xyz, bits(i0|i1<<16))
__device__ float4 g_bb1[PADF];        // (hi.xyz, bits(i2))
__device__ float4 g_tv[NUM_FACES*3];  // per-face vertices (xyz, -)
__device__ float4 g_n[NUM_FACES];     // per-face unit normal (xyz, -)
__device__ float4 g_c[NUM_FACES];     // per-face centroid (xyz, -)
__device__ double g_accum;            // self-resetting
__device__ unsigned g_done;           // self-resetting

// ---------------------------------------------------------------------------
// Kernel 1: FOUR lanes per face (216 blocks x 256 -> 3 scattered loads/lane,
// high occupancy). Lane0 of each quad computes AABB + normal + centroid.
// ---------------------------------------------------------------------------
__global__ void __launch_bounds__(256) setup_kernel(
        const float* __restrict__ verts, const int* __restrict__ faces) {
    int gt = (int)blockIdx.x * 256 + threadIdx.x;  // 216*256 = 55296 = 4*PADF
    int f = gt >> 2;
    int l = gt & 3;
    int wl = threadIdx.x & 31;
    int qb = wl & ~3;                               // quad base lane

    if (f >= PADF) return;
    bool real = f < NUM_FACES;
    int fc = real ? f : (NUM_FACES - 1);            // clamp keeps quads converged
    int comp = (l < 2) ? l : 2;                     // lane 3 duplicates lane 2
    int idx = faces[3 * fc + comp];
    float x = verts[3 * idx + 0];
    float y = verts[3 * idx + 1];
    float z = verts[3 * idx + 2];

    if (real && l < 3) g_tv[f*3 + l] = make_float4(x, y, z, 0.f);

    // gather v1,v2 coords to lane0 of the quad
    float x1 = __shfl_sync(0xffffffffu, x, qb + 1);
    float y1 = __shfl_sync(0xffffffffu, y, qb + 1);
    float z1 = __shfl_sync(0xffffffffu, z, qb + 1);
    float x2 = __shfl_sync(0xffffffffu, x, qb + 2);
    float y2 = __shfl_sync(0xffffffffu, y, qb + 2);
    float z2 = __shfl_sync(0xffffffffu, z, qb + 2);
    int i1 = __shfl_sync(0xffffffffu, idx, qb + 1);
    int i2 = __shfl_sync(0xffffffffu, idx, qb + 2);

    if (l == 0) {
        if (!real) {                                // sentinel: never overlaps
            g_bb0[f] = make_float4(1e30f, 1e30f, 1e30f, __int_as_float(-1));
            g_bb1[f] = make_float4(-1e30f, -1e30f, -1e30f, __int_as_float(-1));
            return;
        }
        float mnx = fminf(x, fminf(x1, x2)), mxx = fmaxf(x, fmaxf(x1, x2));
        float mny = fminf(y, fminf(y1, y2)), mxy = fmaxf(y, fmaxf(y1, y2));
        float mnz = fminf(z, fminf(z1, z2)), mxz = fmaxf(z, fmaxf(z1, z2));
        g_bb0[f] = make_float4(mnx, mny, mnz, __int_as_float(idx | (i1 << 16)));
        g_bb1[f] = make_float4(mxx, mxy, mxz, __int_as_float(i2));

        float e0x = x1-x, e0y = y1-y, e0z = z1-z;
        float e1x = x2-x, e1y = y2-y, e1z = z2-z;
        float nx = e0y*e1z - e0z*e1y;
        float ny = e0z*e1x - e0x*e1z;
        float nz = e0x*e1y - e0y*e1x;
        float inv = 1.0f / (sqrtf(nx*nx + ny*ny + nz*nz) + EPSF);
        g_n[f] = make_float4(nx*inv, ny*inv, nz*inv, 0.f);
        g_c[f] = make_float4((x+x1+x2)*(1.0f/3.0f),
                             (y+y1+y2)*(1.0f/3.0f),
                             (z+z1+z2)*(1.0f/3.0f), 0.f);
    }
}

// Cone-field penalty with precomputed (n, c). SIGMA=0.5 -> *2 exact.
__device__ __forceinline__ float cone_pen_nc(float4 n, float4 c,
                                             float4 p0, float4 p1, float4 p2) {
    float pen = 0.0f;
#pragma unroll
    for (int v = 0; v < 3; v++) {
        float4 p = (v == 0) ? p0 : (v == 1) ? p1 : p2;
        float ux = p.x - c.x, uy = p.y - c.y, uz = p.z - c.z;
        float h = ux*n.x + uy*n.y + uz*n.z;
        float wx = ux - h*n.x, wy = uy - h*n.y, wz = uz - h*n.z;
        float r = sqrtf(wx*wx + wy*wy + wz*wz);
        float radial = fmaxf(1.0f - r*2.0f, 0.0f);
        float depth = fmaxf(-h, 0.0f) + fmaxf(h, 0.0f) * __expf(-h*2.0f);
        float phi = radial * depth;
        pen += phi * phi;
    }
    return pen;
}

__device__ __forceinline__ bool share_ids(int rf0, int rf1, int rf2,
                                          int jp, int jf2) {
    int jf0 = jp & 0xFFFF, jf1 = jp >> 16;
    return (rf0 == jf0) | (rf0 == jf1) | (rf0 == jf2) |
           (rf1 == jf0) | (rf1 == jf1) | (rf1 == jf2) |
           (rf2 == jf0) | (rf2 == jf1) | (rf2 == jf2);
}

// ---------------------------------------------------------------------------
// Kernel 2 (R15 shape — measured 9.9us): TWO rows per warp, single-chunk
// serial ballot scan with shared column loads and early exit; 32-lane eval
// with precomputed normals; fused finalize.
// ---------------------------------------------------------------------------
__global__ void __launch_bounds__(256) collide_kernel(float* __restrict__ out) {
    __shared__ int    s_j[8][16];     // [warp][pair + 8*rowsel]
    __shared__ double s_bsum;

    int tid = threadIdx.x;
    int lane = tid & 31;
    int wwid = tid >> 5;
    int row0 = ((int)blockIdx.x * 8 + wwid) * 2;   // 861*8*2 = 13776 exactly
    int row1 = row0 + 1;
    unsigned below = (1u << lane) - 1u;
    if (tid == 0) s_bsum = 0.0;
    __syncthreads();                               // init visible to all warps

    float4 amin = g_bb0[row0], amax = g_bb1[row0];
    float4 bmin = g_bb0[row1], bmax = g_bb1[row1];
    int ap = __float_as_int(amin.w);
    int af0 = ap & 0xFFFF, af1 = ap >> 16, af2 = __float_as_int(amax.w);
    int bp = __float_as_int(bmin.w);
    int bf0 = bp & 0xFFFF, bf1 = bp >> 16, bf2 = __float_as_int(bmax.w);

    // dual-row serial ballot scan with shared column loads, early exit
    int found0 = 0, found1 = 0;
    for (int base = 0; base < PADF && (found0 < MAXC || found1 < MAXC);
         base += 32) {
        int j = base + lane;
        float4 ja = g_bb0[j];
        float4 jb = g_bb1[j];
        int jp = __float_as_int(ja.w);
        int jf2 = __float_as_int(jb.w);

        bool ok0 = (amin.x <= jb.x) && (ja.x <= amax.x) &&
                   (amin.y <= jb.y) && (ja.y <= amax.y) &&
                   (amin.z <= jb.z) && (ja.z <= amax.z);
        if (ok0) ok0 = !share_ids(af0, af1, af2, jp, jf2);
        bool ok1 = (bmin.x <= jb.x) && (ja.x <= bmax.x) &&
                   (bmin.y <= jb.y) && (ja.y <= bmax.y) &&
                   (bmin.z <= jb.z) && (ja.z <= bmax.z);
        if (ok1) ok1 = !share_ids(bf0, bf1, bf2, jp, jf2);

        unsigned m0 = __ballot_sync(0xffffffffu, ok0);
        unsigned m1 = __ballot_sync(0xffffffffu, ok1);
        int rank0 = found0 + __popc(m0 & below);
        int rank1 = found1 + __popc(m1 & below);
        if (ok0 && rank0 < MAXC) s_j[wwid][rank0] = j;
        if (ok1 && rank1 < MAXC) s_j[wwid][8 + rank1] = j;
        found0 += __popc(m0);
        found1 += __popc(m1);
    }
    if (found0 > MAXC) found0 = MAXC;
    if (found1 > MAXC) found1 = MAXC;
    __syncwarp();

    // narrow phase: 32 lanes -> (row l>>4) x (pair (l&15)>>1) x (dir l&1)
    int rowsel = lane >> 4;
    int l = lane & 15;
    int pairIdx = l >> 1;
    int cnt = rowsel ? found1 : found0;
    float pen = 0.0f;
    if (pairIdx < cnt) {
        int row = rowsel ? row1 : row0;
        int j = s_j[wwid][(rowsel << 3) + pairIdx];
        int srcF = (l & 1) ? j : row;              // field-generating tri
        int ptsF = (l & 1) ? row : j;              // query vertices
        float4 n = g_n[srcF];
        float4 c = g_c[srcF];
        float4 p0 = g_tv[ptsF*3+0];
        float4 p1 = g_tv[ptsF*3+1];
        float4 p2 = g_tv[ptsF*3+2];
        pen = cone_pen_nc(n, c, p0, p1, p2);
    }
#pragma unroll
    for (int off = 16; off > 0; off >>= 1)
        pen += __shfl_xor_sync(0xffffffffu, pen, off);
    if (lane == 0 && pen != 0.0f) atomicAdd(&s_bsum, (double)pen);
    __syncthreads();

    // fused finalize: last-arriving block writes output + resets state
    if (tid == 0) {
        if (s_bsum != 0.0) atomicAdd(&g_accum, s_bsum);
        __threadfence();
        unsigned old = atomicAdd(&g_done, 1u);
        if (old == K2_BLOCKS - 1) {
            g_done = 0;                             // reset for graph replay
            unsigned long long bits =
                atomicExch((unsigned long long*)&g_accum, 0ULL);
            out[0] = (float)__longlong_as_double(bits);  // weight = 1.0
        }
    }
}

extern "C" void kernel_launch(void* const* d_in, const int* in_sizes, int n_in,
                              void* d_out, int out_size) {
    const float* verts = (const float*)d_in[0];
    const int*   faces = (const int*)d_in[1];
    float*       out   = (float*)d_out;

    setup_kernel<<<(4 * PADF) / 256, 256>>>(verts, faces);
    collide_kernel<<<K2_BLOCKS, 256>>>(out);
}